// round 5
// baseline (speedup 1.0000x reference)
#include <cuda_runtime.h>

// Fixed problem shape: B=16, C=1, H=128, W=8192, NMAX=64
#define BB   16
#define HH   128
#define WW   8192
#define NMX  64
#define BIGQ 0x3FFFFFFF

#define COPY_BLOCKS (BB * NMX)        // 1024: one per (batch, segment)
#define ZERO_PER_B  64                // 8 col-chunks x 8 row-chunks
#define ZERO_BLOCKS (BB * ZERO_PER_B) // 1024
#define NBLK (COPY_BLOCKS + ZERO_BLOCKS)

// ---------------------------------------------------------------------------
// One flat grid, two block roles.
//  Copy block (b,seg): contiguous copy of w columns x 128 rows from
//    x[b][:, s:s+w] to out[b][:, sn:sn+w], plus sep column at sn+w when
//    seg < n-1. Block (b,0) also writes xi_new to the output tail.
//  Zero block: streams float4 zeros into columns [E, W) of its chunk, where
//    E = end of last valid segment (everything before E is covered exactly
//    by copy blocks; layout is contiguous: next_start = end + 1).
// ---------------------------------------------------------------------------
__global__ void __launch_bounds__(256)
pack_kernel(const float* __restrict__ x,
            const int*   __restrict__ xi,
            const int*   __restrict__ N,
            const float* __restrict__ sep_param,
            float* __restrict__ out,
            float* __restrict__ out_xi,
            int write_xi) {
    const int blk = blockIdx.x;
    const int t   = threadIdx.x;

    if (blk < COPY_BLOCKS) {
        // ================= COPY ROLE =================
        const int b   = blk >> 6;
        const int seg = blk & 63;

        __shared__ int   sh_w0;
        __shared__ int   sh_sn, sh_en, sh_s, sh_valid, sh_n;
        __shared__ float sh_sep;

        if (t == 0) { sh_n = N[b]; sh_sep = sep_param[0]; }
        __syncthreads();
        const int n = sh_n;

        int s = 0, wv = 0, valid = 0, sc = 0;
        if (t < NMX) {
            s = xi[(b * NMX + t) * 2 + 0];
            const int e = xi[(b * NMX + t) * 2 + 1];
            valid = (t < n) ? 1 : 0;
            wv = valid ? max(e - s, 0) : 0;
            sc = wv;
            #pragma unroll
            for (int off = 1; off < 32; off <<= 1) {
                int v = __shfl_up_sync(0xFFFFFFFFu, sc, off);
                if ((t & 31) >= off) sc += v;
            }
            if (t == 31) sh_w0 = sc;
        }
        __syncthreads();
        if (t < NMX) {
            const int csum = sc + ((t >= 32) ? sh_w0 : 0);
            const int sn = csum - wv + t;
            const int en = csum + t;
            if (t == seg) {
                sh_sn = sn; sh_en = en; sh_s = s; sh_valid = valid;
            }
            if (write_xi && seg == 0) {
                out_xi[(b * NMX + t) * 2 + 0] = valid ? (float)sn : 0.0f;
                out_xi[(b * NMX + t) * 2 + 1] = valid ? (float)en : 0.0f;
            }
        }
        __syncthreads();

        if (!sh_valid) return;

        const int   w    = sh_en - sh_sn;
        const int   wext = w + ((seg < n - 1) ? 1 : 0);   // sep column folded in
        const float sep  = sh_sep;
        const int   lane = t & 31;
        const int   wg   = t >> 5;                         // 8 row groups

        const float* __restrict__ srow0 = x   + (size_t)b * HH * WW + sh_s;
        float* __restrict__       drow0 = out + (size_t)b * HH * WW + sh_sn;

        // Up to 3 column slots per lane (wext <= 89 < 96).
        const int  c0 = lane, c1 = lane + 32, c2 = lane + 64;
        const bool a0 = c0 < wext, a1 = c1 < wext, a2 = c2 < wext;
        const bool g0 = c0 < w,    g1 = c1 < w,    g2 = c2 < w;

        #pragma unroll 4
        for (int r = wg; r < HH; r += 8) {
            const float* __restrict__ srow = srow0 + (size_t)r * WW;
            float* __restrict__       drow = drow0 + (size_t)r * WW;
            if (a0) drow[c0] = g0 ? __ldg(srow + c0) : sep;
            if (a1) drow[c1] = g1 ? __ldg(srow + c1) : sep;
            if (a2) drow[c2] = g2 ? __ldg(srow + c2) : sep;
        }
    } else {
        // ================= ZERO ROLE =================
        const int zb = blk - COPY_BLOCKS;
        const int b  = zb >> 6;
        const int cc = (zb >> 3) & 7;   // col chunk: 1024 cols
        const int rc = zb & 7;          // row chunk: 16 rows

        __shared__ int sh_sum[2];
        __shared__ int sh_n;

        if (t == 0) sh_n = N[b];
        __syncthreads();
        const int n = sh_n;

        if (t < NMX) {
            const int s = xi[(b * NMX + t) * 2 + 0];
            const int e = xi[(b * NMX + t) * 2 + 1];
            int wv = (t < n) ? max(e - s, 0) : 0;
            #pragma unroll
            for (int off = 16; off > 0; off >>= 1)
                wv += __shfl_down_sync(0xFFFFFFFFu, wv, off);
            if ((t & 31) == 0) sh_sum[t >> 5] = wv;
        }
        __syncthreads();
        const int E = sh_sum[0] + sh_sum[1] + n - 1;   // zeros for j >= E

        const int j0 = cc * 1024 + t * 4;
        if (j0 + 3 < E) return;

        float* __restrict__ ob = out + (size_t)b * HH * WW + (size_t)(rc * 16) * WW;
        if (j0 >= E) {
            const float4 z = make_float4(0.f, 0.f, 0.f, 0.f);
            #pragma unroll 4
            for (int r = 0; r < 16; r++)
                *reinterpret_cast<float4*>(ob + (size_t)r * WW + j0) = z;
        } else {
            // straddles E: scalar tail
            #pragma unroll
            for (int c = 0; c < 4; c++) {
                const int j = j0 + c;
                if (j >= E) {
                    for (int r = 0; r < 16; r++)
                        ob[(size_t)r * WW + j] = 0.0f;
                }
            }
        }
    }
}

// ---------------------------------------------------------------------------
extern "C" void kernel_launch(void* const* d_in, const int* in_sizes, int n_in,
                              void* d_out, int out_size) {
    const float* x   = (const float*)d_in[0];
    const int*   xi  = (const int*)  d_in[1];
    const int*   N   = (const int*)  d_in[2];
    const float* sep = (const float*)d_in[3];
    float*       out = (float*)d_out;

    const long long XN = (long long)BB * HH * WW;   // 16,777,216
    const int write_xi = ((long long)out_size > XN) ? 1 : 0;

    pack_kernel<<<NBLK, 256>>>(x, xi, N, sep, out, out + XN, write_xi);
}

// round 6
// speedup vs baseline: 1.7145x; 1.7145x over previous
#include <cuda_runtime.h>

// Fixed problem shape: B=16, C=1, H=128, W=8192, NMAX=64
#define BB   16
#define HH   128
#define WW   8192
#define NMX  64
#define ROWS_PER_BLOCK 16       // grid.z = 8
#define BIGV 0x3FFFFFFF

// Scratch for segment metadata (allocation-free rule: device globals)
__device__ int g_start[BB][NMX];
__device__ int g_end[BB][NMX];
__device__ int g_src0[BB][NMX];
__device__ int g_n[BB];

// ---------------------------------------------------------------------------
// Kernel 1: per-batch metadata. 16 blocks x 64 threads. Prefix-scan of chirp
// widths -> compressed starts/ends; writes xi_new to output tail.
// ---------------------------------------------------------------------------
__global__ void meta_kernel(const int* __restrict__ xi,
                            const int* __restrict__ N,
                            float* __restrict__ out_xi,
                            int write_xi) {
    const int b = blockIdx.x;
    const int i = threadIdx.x;            // 0..63
    __shared__ int sh_w0;

    const int n = N[b];
    const int s = xi[(b * NMX + i) * 2 + 0];
    const int e = xi[(b * NMX + i) * 2 + 1];
    const int valid = (i < n) ? 1 : 0;
    const int wv = valid ? max(e - s, 0) : 0;

    int sc = wv;
    #pragma unroll
    for (int off = 1; off < 32; off <<= 1) {
        int v = __shfl_up_sync(0xFFFFFFFFu, sc, off);
        if ((i & 31) >= off) sc += v;
    }
    if (i == 31) sh_w0 = sc;
    __syncthreads();
    const int csum = sc + ((i >= 32) ? sh_w0 : 0);
    const int sn = csum - wv + i;         // compressed start
    const int en = csum + i;              // compressed end

    g_start[b][i] = valid ? sn : BIGV;    // sentinel keeps array sorted
    g_end[b][i]   = en;
    g_src0[b][i]  = s;
    if (i == 0) g_n[b] = n;

    if (write_xi) {
        out_xi[(b * NMX + i) * 2 + 0] = valid ? (float)sn : 0.0f;
        out_xi[(b * NMX + i) * 2 + 1] = valid ? (float)en : 0.0f;
    }
}

// ---------------------------------------------------------------------------
// Kernel 2: pack/gather. grid = (WW/1024=8, BB=16, HH/16=8) = 1024 blocks,
// block = 256. Each thread owns 4 consecutive columns x 16 rows.
// ONE binary search per thread (segments are contiguous and >=21 wide, so
// 4 consecutive columns cross at most one boundary). float4 streaming stores.
// ---------------------------------------------------------------------------
__global__ void __launch_bounds__(256)
pack_kernel(const float* __restrict__ x,
            const float* __restrict__ sep_param,
            float* __restrict__ out) {
    const int b = blockIdx.y;
    const int t = threadIdx.x;

    __shared__ int   s_start[NMX + 1];   // +1 sentinel slot
    __shared__ int   s_end[NMX];
    __shared__ int   s_src[NMX];
    __shared__ int   s_n;
    __shared__ float s_sep;

    if (t < NMX) {
        s_start[t] = g_start[b][t];
        s_end[t]   = g_end[b][t];
        s_src[t]   = g_src0[b][t];
    }
    if (t == 0) { s_n = g_n[b]; s_sep = sep_param[0]; s_start[NMX] = BIGV; }
    __syncthreads();

    const int n  = s_n;
    const int j0 = (blockIdx.x * 256 + t) * 4;

    // upper_bound(start, j0) - 1 ; start[0] == 0 so seg >= 0 for all j0 >= 0
    int lo = 0, hi = n;
    while (lo < hi) {
        int mid = (lo + hi) >> 1;
        if (s_start[mid] <= j0) lo = mid + 1; else hi = mid;
    }
    int cur = lo - 1;

    bool  gth[4];
    int   src[4];
    float fil[4];
    #pragma unroll
    for (int c = 0; c < 4; c++) {
        const int j = j0 + c;
        if (j >= s_start[cur + 1]) cur++;     // at most once over 4 columns
        gth[c] = false; src[c] = 0; fil[c] = 0.0f;
        if (cur >= 0) {
            const int s = s_start[cur];
            const int e = s_end[cur];
            if (j < e) {
                gth[c] = true;
                src[c] = min(max(s_src[cur] + (j - s), 0), WW - 1);
            } else if (j == e && cur < n - 1) {
                fil[c] = s_sep;
            }
        }
    }

    const int h0 = blockIdx.z * ROWS_PER_BLOCK;
    const float* __restrict__ xb = x   + (size_t)b * HH * WW + (size_t)h0 * WW;
    float* __restrict__       ob = out + (size_t)b * HH * WW + (size_t)h0 * WW;

    #pragma unroll 4
    for (int hh = 0; hh < ROWS_PER_BLOCK; hh++) {
        const size_t row = (size_t)hh * WW;
        float4 v;
        v.x = gth[0] ? __ldg(xb + row + src[0]) : fil[0];
        v.y = gth[1] ? __ldg(xb + row + src[1]) : fil[1];
        v.z = gth[2] ? __ldg(xb + row + src[2]) : fil[2];
        v.w = gth[3] ? __ldg(xb + row + src[3]) : fil[3];
        __stcs(reinterpret_cast<float4*>(ob + row + j0), v);
    }
}

// ---------------------------------------------------------------------------
extern "C" void kernel_launch(void* const* d_in, const int* in_sizes, int n_in,
                              void* d_out, int out_size) {
    const float* x   = (const float*)d_in[0];
    const int*   xi  = (const int*)  d_in[1];
    const int*   N   = (const int*)  d_in[2];
    const float* sep = (const float*)d_in[3];
    float*       out = (float*)d_out;

    const long long XN = (long long)BB * HH * WW;   // 16,777,216
    const int write_xi = ((long long)out_size > XN) ? 1 : 0;

    meta_kernel<<<BB, NMX>>>(xi, N, out + XN, write_xi);

    dim3 grid(WW / (256 * 4), BB, HH / ROWS_PER_BLOCK);
    pack_kernel<<<grid, 256>>>(x, sep, out);
}